// round 12
// baseline (speedup 1.0000x reference)
#include <cuda_runtime.h>

// 13 packed coefficient pairs (out0,out1), padded to 7 float4:
//  q0=(T0,T1) q1=(T2,T3) q2=(T4,T5) q3=(T6,T7) q4=(T8,U0) q5=(U1,U2) q6=(U3,pad)
__device__ float4 g_T[7];

// ---------------------------------------------------------------------------
// Precompute: ONE warp. Circuit structure (validated R7-R11): CNOT(0,1)
// couples only wires 0,1 -> U factorizes as (W on q0q1) x V2 x V3 with
// M_i = RY(w1)*RZ(w0), W = (C*(M0 kron M1))^2, V_i = M_i^2. Fold
// head_w/head_b into 13 coefficients:
//   out_j = Horner9(T; cos x0, sin x0, cos x1, sin x1)
//         + U0 cos x2 + U1 sin x2 + U2 cos x3 + U3 sin x3
// Triggers programmatic launch completion FIRST so the main grid overlaps.
// ---------------------------------------------------------------------------
__global__ void precompute_kernel(const float* __restrict__ w,
                                  const float* __restrict__ hw,
                                  const float* __restrict__ hb) {
    cudaTriggerProgrammaticLaunchCompletion();

    __shared__ float2 sM[4][4];    // per-wire 2x2 M_i
    __shared__ float2 sN[16];      // N = C*(M0 kron M1)
    __shared__ float2 sW[16];      // W = N*N
    __shared__ float  sG[2][16];   // G_j = Re(W^H Z_j W)
    __shared__ float  sS[2][3];    // singles (a,b,d) for wires 2,3
    __shared__ float  sOut[28];

    const int t = threadIdx.x;     // 0..31

    if (t < 4) {
        float sz, cz, sy, cy;
        __sincosf(0.5f * w[t * 4 + 0], &sz, &cz);   // RZ half-angle
        __sincosf(0.5f * w[t * 4 + 1], &sy, &cy);   // RY half-angle
        // M = RY*RZ, e = cz - i sz:  [[cy*e, -sy*e*],[sy*e, cy*e*]]
        sM[t][0] = make_float2( cy * cz, -cy * sz);
        sM[t][1] = make_float2(-sy * cz, -sy * sz);
        sM[t][2] = make_float2( sy * cz, -sy * sz);
        sM[t][3] = make_float2( cy * cz,  cy * sz);
    }
    __syncwarp();
    if (t < 16) {
        // N = C * (M0 kron M1); CNOT permutes rows 2<->3.
        const int r = t >> 2, c = t & 3;
        const int rr = (r == 2) ? 3 : (r == 3) ? 2 : r;
        const float2 a = sM[0][(rr >> 1) * 2 + (c >> 1)];
        const float2 b = sM[1][(rr & 1) * 2 + (c & 1)];
        sN[t] = make_float2(a.x * b.x - a.y * b.y, a.x * b.y + a.y * b.x);
    } else if (t < 18) {
        // Singles: wire q = t-14 (2 or 3). V = M^2, P = V^H Z V.
        const float2* M = sM[t - 14];
        float2 V[4];
        #pragma unroll
        for (int r = 0; r < 2; ++r)
            #pragma unroll
            for (int c = 0; c < 2; ++c) {
                const float2 p = M[r * 2 + 0], q = M[0 * 2 + c];
                const float2 p2 = M[r * 2 + 1], q2 = M[1 * 2 + c];
                V[r * 2 + c] = make_float2(
                    p.x * q.x - p.y * q.y + p2.x * q2.x - p2.y * q2.y,
                    p.x * q.y + p.y * q.x + p2.x * q2.y + p2.y * q2.x);
            }
        const float p00 = V[0].x * V[0].x + V[0].y * V[0].y
                        - (V[2].x * V[2].x + V[2].y * V[2].y);
        const float p11 = V[1].x * V[1].x + V[1].y * V[1].y
                        - (V[3].x * V[3].x + V[3].y * V[3].y);
        const float rp01 = V[0].x * V[1].x + V[0].y * V[1].y
                         - (V[2].x * V[3].x + V[2].y * V[3].y);
        sS[t - 16][0] = 0.5f * (p00 + p11);   // a (constant)
        sS[t - 16][1] = 0.5f * (p00 - p11);   // b (cos coef)
        sS[t - 16][2] = rp01;                 // d (sin coef)
    }
    __syncwarp();
    if (t < 16) {
        // W = N * N (4x4 complex)
        const int r = t >> 2, c = t & 3;
        float ar = 0.0f, ai = 0.0f;
        #pragma unroll
        for (int k = 0; k < 4; ++k) {
            const float2 u = sN[r * 4 + k];
            const float2 v = sN[k * 4 + c];
            ar += u.x * v.x - u.y * v.y;
            ai += u.x * v.y + u.y * v.x;
        }
        sW[t] = make_float2(ar, ai);
    }
    __syncwarp();
    {
        // G_j[k][m] = sum_r zsign_j(r) * Re(conj(W[r,k]) W[r,m])
        const int j = t >> 4, k = (t >> 2) & 3, m = t & 3;
        float g = 0.0f;
        #pragma unroll
        for (int r = 0; r < 4; ++r) {
            const float zs = (j == 0) ? ((r & 2) ? -1.0f : 1.0f)
                                      : ((r & 1) ? -1.0f : 1.0f);
            g += zs * (sW[r * 4 + k].x * sW[r * 4 + m].x +
                       sW[r * 4 + k].y * sW[r * 4 + m].y);
        }
        sG[j][k * 4 + m] = g;
    }
    __syncwarp();
    if (t < 9) {
        // T[e0][e1]: (c^2,cs,s^2) -> (1,cos,sin) transform per axis.
        const float F[3][3] = {{0.5f, 0.5f, 0.0f},
                               {0.0f, 0.0f, 0.5f},
                               {0.5f, -0.5f, 0.0f}};
        const int e0 = t / 3, e1 = t % 3;
        const float hw00 = hw[0], hw01 = hw[1], hw10 = hw[4], hw11 = hw[5];
        float a0 = 0.0f, a1 = 0.0f;
        #pragma unroll
        for (int k = 0; k < 4; ++k)
            #pragma unroll
            for (int m = 0; m < 4; ++m) {
                const int d0 = (k >> 1) + (m >> 1);
                const int d1 = (k & 1) + (m & 1);
                const float ww = F[d0][e0] * F[d1][e1];
                const float g0 = sG[0][k * 4 + m];
                const float g1 = sG[1][k * 4 + m];
                a0 += ww * (hw00 * g0 + hw01 * g1);
                a1 += ww * (hw10 * g0 + hw11 * g1);
            }
        if (t == 0) {  // fold bias + singles' constant terms
            a0 += hb[0] + hw[2] * sS[0][0] + hw[3] * sS[1][0];
            a1 += hb[1] + hw[6] * sS[0][0] + hw[7] * sS[1][0];
        }
        sOut[2 * t]     = a0;   // T_t
        sOut[2 * t + 1] = a1;
    } else if (t < 13) {
        const int q = (t - 9) >> 1;       // 0 -> wire2, 1 -> wire3
        const int which = (t - 9) & 1;    // 0 -> b (cos), 1 -> d (sin)
        const float v = sS[q][1 + which];
        sOut[2 * t]     = hw[2 + q] * v;  // U_{t-9}
        sOut[2 * t + 1] = hw[6 + q] * v;
    } else if (t < 15) {
        sOut[2 * t]     = 0.0f;           // pad
        sOut[2 * t + 1] = 0.0f;
    }
    __syncwarp();
    if (t < 7) {
        g_T[t] = make_float4(sOut[4 * t], sOut[4 * t + 1],
                             sOut[4 * t + 2], sOut[4 * t + 3]);
    }
}

// ---------------------------------------------------------------------------
// Main kernel (PDL downstream): barrier-free, smem-free. Per thread: one
// float4 load + 4 __sincosf BEFORE the grid dependency sync (overlaps the
// upstream precompute), then 7 broadcast LDG.128 of the table + 24 FFMA +
// one float2 store.
// ---------------------------------------------------------------------------
__global__ void __launch_bounds__(256, 5)
main_kernel(const float4* __restrict__ x4,
            float2* __restrict__ out2,
            int B) {
    const int i = blockIdx.x * 256 + threadIdx.x;

    const float4 xv = (i < B) ? x4[i] : make_float4(0.f, 0.f, 0.f, 0.f);
    float sn0, cn0, sn1, cn1, sn2, cn2, sn3, cn3;
    __sincosf(xv.x, &sn0, &cn0);
    __sincosf(xv.y, &sn1, &cn1);
    __sincosf(xv.z, &sn2, &cn2);
    __sincosf(xv.w, &sn3, &cn3);

    cudaGridDependencySynchronize();

    const float4 q0 = g_T[0];   // (T0x,T0y,T1x,T1y)
    const float4 q1 = g_T[1];   // (T2x,T2y,T3x,T3y)
    const float4 q2 = g_T[2];   // (T4x,T4y,T5x,T5y)
    const float4 q3 = g_T[3];   // (T6x,T6y,T7x,T7y)
    const float4 q4 = g_T[4];   // (T8x,T8y,U0x,U0y)
    const float4 q5 = g_T[5];   // (U1x,U1y,U2x,U2y)
    const float4 q6 = g_T[6];   // (U3x,U3y,pad,pad)

    const float e0x = fmaf(sn1, q1.x, fmaf(cn1, q0.z, q0.x));
    const float e0y = fmaf(sn1, q1.y, fmaf(cn1, q0.w, q0.y));
    const float e1x = fmaf(sn1, q2.z, fmaf(cn1, q2.x, q1.z));
    const float e1y = fmaf(sn1, q2.w, fmaf(cn1, q2.y, q1.w));
    const float e2x = fmaf(sn1, q4.x, fmaf(cn1, q3.z, q3.x));
    const float e2y = fmaf(sn1, q4.y, fmaf(cn1, q3.w, q3.y));

    float rx = fmaf(sn0, e2x, fmaf(cn0, e1x, e0x));
    float ry = fmaf(sn0, e2y, fmaf(cn0, e1y, e0y));
    rx = fmaf(cn2, q4.z, rx);  ry = fmaf(cn2, q4.w, ry);
    rx = fmaf(sn2, q5.x, rx);  ry = fmaf(sn2, q5.y, ry);
    rx = fmaf(cn3, q5.z, rx);  ry = fmaf(cn3, q5.w, ry);
    rx = fmaf(sn3, q6.x, rx);  ry = fmaf(sn3, q6.y, ry);

    if (i < B) out2[i] = make_float2(rx, ry);
}

extern "C" void kernel_launch(void* const* d_in, const int* in_sizes, int n_in,
                              void* d_out, int out_size) {
    const float* x  = (const float*)d_in[0];   // (B, 4) fp32
    const float* w  = (const float*)d_in[1];   // (2, 4, 4) fp32
    const float* hw = (const float*)d_in[2];   // (2, 4) fp32
    const float* hb = (const float*)d_in[3];   // (2,) fp32

    const int B = in_sizes[0] / 4;
    const int grid = (B + 255) / 256;

    // Upstream: one-warp table build; triggers launch completion immediately.
    precompute_kernel<<<1, 32>>>(w, hw, hb);

    // Downstream: PDL — prologue (x load + trig) overlaps the upstream;
    // gates on cudaGridDependencySynchronize() before reading the table.
    cudaLaunchConfig_t cfg = {};
    cfg.gridDim  = dim3((unsigned)grid, 1, 1);
    cfg.blockDim = dim3(256, 1, 1);
    cfg.dynamicSmemBytes = 0;
    cfg.stream = 0;
    cudaLaunchAttribute attrs[1];
    attrs[0].id = cudaLaunchAttributeProgrammaticStreamSerialization;
    attrs[0].val.programmaticStreamSerializationAllowed = 1;
    cfg.attrs = attrs;
    cfg.numAttrs = 1;

    cudaLaunchKernelEx(&cfg, main_kernel,
                       (const float4*)x, (float2*)d_out, B);
}

// round 13
// speedup vs baseline: 1.2657x; 1.2657x over previous
#include <cuda_runtime.h>
#include <cstdint>

// ---------------------------------------------------------------------------
// Async-copy + mbarrier helpers
// ---------------------------------------------------------------------------
__device__ __forceinline__ uint32_t smem_u32(const void* p) {
    return (uint32_t)__cvta_generic_to_shared(p);
}
__device__ __forceinline__ void mbar_init(uint32_t mbar, uint32_t count) {
    asm volatile("mbarrier.init.shared.b64 [%0], %1;" :: "r"(mbar), "r"(count) : "memory");
}
__device__ __forceinline__ void mbar_expect_tx(uint32_t mbar, uint32_t bytes) {
    asm volatile("mbarrier.arrive.expect_tx.shared.b64 _, [%0], %1;"
                 :: "r"(mbar), "r"(bytes) : "memory");
}
__device__ __forceinline__ void mbar_wait(uint32_t mbar, uint32_t parity) {
    asm volatile(
        "{\n\t"
        ".reg .pred P1;\n\t"
        "WAIT_LOOP_%=:\n\t"
        "mbarrier.try_wait.parity.acquire.cta.shared::cta.b64 P1, [%0], %1, 0x989680;\n\t"
        "@P1 bra.uni WAIT_DONE_%=;\n\t"
        "bra.uni WAIT_LOOP_%=;\n\t"
        "WAIT_DONE_%=:\n\t"
        "}"
        :: "r"(mbar), "r"(parity) : "memory");
}
__device__ __forceinline__ void bulk_g2s(uint32_t dst, const void* src,
                                         uint32_t bytes, uint32_t mbar) {
    asm volatile(
        "cp.async.bulk.shared::cta.global.mbarrier::complete_tx::bytes [%0], [%1], %2, [%3];"
        :: "r"(dst), "l"(src), "r"(bytes), "r"(mbar) : "memory");
}

// ---------------------------------------------------------------------------
// Structure (validated R7-R12): CNOT(0,1) couples only wires 0,1 -> circuit
// factorizes; folding head_w/head_b gives 13 coefficient pairs:
//   out_j = Horner9(T; cos x0, sin x0, cos x1, sin x1)
//         + U0 cos x2 + U1 sin x2 + U2 cos x3 + U3 sin x3
// R13: persistent blocks + double-buffered cp.async.bulk pipeline so x-load
// latency is off every warp's critical path. Phase A (warp 0) overlaps the
// first bulk copy (issued by warp 7). One __syncthreads per iteration.
// ---------------------------------------------------------------------------
#define CHUNK 256              // samples per chunk = 4KB of x, 1 per thread

__global__ void __launch_bounds__(256)
fused_kernel(const float4* __restrict__ x4,
             float2* __restrict__ out2,
             const float* __restrict__ w,
             const float* __restrict__ hw,
             const float* __restrict__ hb,
             int nchunks, int B) {
    __shared__ float4 buf[2][CHUNK];           // double buffer, 2 x 4KB
    __shared__ uint64_t mbar_store[2];
    // Phase A scratch
    __shared__ float2 sM[4][4];
    __shared__ float2 sN[16];
    __shared__ float2 sW[16];
    __shared__ float  sG[2][16];
    __shared__ float  sS[2][3];
    __shared__ float2 sT[9];
    __shared__ float2 sU[4];

    const int t = threadIdx.x;
    const uint32_t mb0 = smem_u32(&mbar_store[0]);
    const uint32_t mb1 = smem_u32(&mbar_store[1]);
    const uint32_t bufaddr0 = smem_u32(&buf[0][0]);
    const uint32_t bufaddr1 = smem_u32(&buf[1][0]);

    const int c0 = blockIdx.x;           // first chunk for this block
    const int cstride = gridDim.x;

    // ---- producer prologue (warp 7): init barriers, kick first copy
    if (t == 224) {
        mbar_init(mb0, 1);
        mbar_init(mb1, 1);
        asm volatile("fence.proxy.async.shared::cta;" ::: "memory");
        if (c0 < nchunks) {
            mbar_expect_tx(mb0, CHUNK * 16);
            bulk_g2s(bufaddr0, x4 + (size_t)c0 * CHUNK, CHUNK * 16, mb0);
        }
    }

    // ================= Phase A: warp 0, syncwarp-staged =================
    if (t < 32) {
        if (t < 4) {
            float sz, cz, sy, cy;
            __sincosf(0.5f * w[t * 4 + 0], &sz, &cz);   // RZ half-angle
            __sincosf(0.5f * w[t * 4 + 1], &sy, &cy);   // RY half-angle
            // M = RY*RZ, e = cz - i sz:  [[cy*e, -sy*e*],[sy*e, cy*e*]]
            sM[t][0] = make_float2( cy * cz, -cy * sz);
            sM[t][1] = make_float2(-sy * cz, -sy * sz);
            sM[t][2] = make_float2( sy * cz, -sy * sz);
            sM[t][3] = make_float2( cy * cz,  cy * sz);
        }
        __syncwarp();
        if (t < 16) {
            // N = C * (M0 kron M1); CNOT permutes rows 2<->3.
            const int r = t >> 2, c = t & 3;
            const int rr = (r == 2) ? 3 : (r == 3) ? 2 : r;
            const float2 a = sM[0][(rr >> 1) * 2 + (c >> 1)];
            const float2 b = sM[1][(rr & 1) * 2 + (c & 1)];
            sN[t] = make_float2(a.x * b.x - a.y * b.y, a.x * b.y + a.y * b.x);
        } else if (t < 18) {
            // Singles: wire q = t-14 (2 or 3). V = M^2, P = V^H Z V.
            const float2* M = sM[t - 14];
            float2 V[4];
            #pragma unroll
            for (int r = 0; r < 2; ++r)
                #pragma unroll
                for (int c = 0; c < 2; ++c) {
                    const float2 p = M[r * 2 + 0], q = M[0 * 2 + c];
                    const float2 p2 = M[r * 2 + 1], q2 = M[1 * 2 + c];
                    V[r * 2 + c] = make_float2(
                        p.x * q.x - p.y * q.y + p2.x * q2.x - p2.y * q2.y,
                        p.x * q.y + p.y * q.x + p2.x * q2.y + p2.y * q2.x);
                }
            const float p00 = V[0].x * V[0].x + V[0].y * V[0].y
                            - (V[2].x * V[2].x + V[2].y * V[2].y);
            const float p11 = V[1].x * V[1].x + V[1].y * V[1].y
                            - (V[3].x * V[3].x + V[3].y * V[3].y);
            const float rp01 = V[0].x * V[1].x + V[0].y * V[1].y
                             - (V[2].x * V[3].x + V[2].y * V[3].y);
            sS[t - 16][0] = 0.5f * (p00 + p11);   // a (constant)
            sS[t - 16][1] = 0.5f * (p00 - p11);   // b (cos coef)
            sS[t - 16][2] = rp01;                 // d (sin coef)
        }
        __syncwarp();
        if (t < 16) {
            // W = N * N (4x4 complex)
            const int r = t >> 2, c = t & 3;
            float ar = 0.0f, ai = 0.0f;
            #pragma unroll
            for (int k = 0; k < 4; ++k) {
                const float2 u = sN[r * 4 + k];
                const float2 v = sN[k * 4 + c];
                ar += u.x * v.x - u.y * v.y;
                ai += u.x * v.y + u.y * v.x;
            }
            sW[t] = make_float2(ar, ai);
        }
        __syncwarp();
        {
            // G_j[k][m] = sum_r zsign_j(r) * Re(conj(W[r,k]) W[r,m])
            const int j = t >> 4, k = (t >> 2) & 3, m = t & 3;
            float g = 0.0f;
            #pragma unroll
            for (int r = 0; r < 4; ++r) {
                const float zs = (j == 0) ? ((r & 2) ? -1.0f : 1.0f)
                                          : ((r & 1) ? -1.0f : 1.0f);
                g += zs * (sW[r * 4 + k].x * sW[r * 4 + m].x +
                           sW[r * 4 + k].y * sW[r * 4 + m].y);
            }
            sG[j][k * 4 + m] = g;
        }
        __syncwarp();
        if (t < 9) {
            // (c^2,cs,s^2) -> (1,cos,sin) transform per axis.
            const float F[3][3] = {{0.5f, 0.5f, 0.0f},
                                   {0.0f, 0.0f, 0.5f},
                                   {0.5f, -0.5f, 0.0f}};
            const int e0 = t / 3, e1 = t % 3;
            const float hw00 = hw[0], hw01 = hw[1], hw10 = hw[4], hw11 = hw[5];
            float a0 = 0.0f, a1 = 0.0f;
            #pragma unroll
            for (int k = 0; k < 4; ++k)
                #pragma unroll
                for (int m = 0; m < 4; ++m) {
                    const int d0 = (k >> 1) + (m >> 1);
                    const int d1 = (k & 1) + (m & 1);
                    const float ww = F[d0][e0] * F[d1][e1];
                    const float g0 = sG[0][k * 4 + m];
                    const float g1 = sG[1][k * 4 + m];
                    a0 += ww * (hw00 * g0 + hw01 * g1);
                    a1 += ww * (hw10 * g0 + hw11 * g1);
                }
            if (t == 0) {  // fold bias + singles' constant terms
                a0 += hb[0] + hw[2] * sS[0][0] + hw[3] * sS[1][0];
                a1 += hb[1] + hw[6] * sS[0][0] + hw[7] * sS[1][0];
            }
            sT[t] = make_float2(a0, a1);
        } else if (t < 13) {
            const int q = (t - 9) >> 1;       // 0 -> wire2, 1 -> wire3
            const int which = (t - 9) & 1;    // 0 -> b (cos), 1 -> d (sin)
            const float v = sS[q][1 + which];
            sU[t - 9] = make_float2(hw[2 + q] * v, hw[6 + q] * v);
        }
    }
    __syncthreads();   // publishes sT/sU and mbarrier init

    // ---- table (warp-uniform LDS broadcasts, hoisted once)
    const float2 T0 = sT[0], T1 = sT[1], T2 = sT[2];
    const float2 T3 = sT[3], T4 = sT[4], T5 = sT[5];
    const float2 T6 = sT[6], T7 = sT[7], T8 = sT[8];
    const float2 U0 = sU[0], U1 = sU[1], U2 = sU[2], U3 = sU[3];

    // ================= chunk loop: double-buffered pipeline =================
    int phase0 = 0, phase1 = 0;
    int k = 0;
    for (int c = c0; c < nchunks; c += cstride, ++k) {
        const int cur = k & 1;
        // prefetch next chunk into the other buffer (its readers finished at
        // iteration k-1; the __syncthreads at the end of k-1 ordered them)
        const int nc = c + cstride;
        if (t == 224 && nc < nchunks) {
            const uint32_t mbn = cur ? mb0 : mb1;
            mbar_expect_tx(mbn, CHUNK * 16);
            bulk_g2s(cur ? bufaddr0 : bufaddr1,
                     x4 + (size_t)nc * CHUNK, CHUNK * 16, mbn);
        }
        // wait for current buffer
        if (cur) { mbar_wait(mb1, phase1); phase1 ^= 1; }
        else     { mbar_wait(mb0, phase0); phase0 ^= 1; }

        const float4 xv = buf[cur][t];
        float sn0, cn0, sn1, cn1, sn2, cn2, sn3, cn3;
        __sincosf(xv.x, &sn0, &cn0);
        __sincosf(xv.y, &sn1, &cn1);
        __sincosf(xv.z, &sn2, &cn2);
        __sincosf(xv.w, &sn3, &cn3);

        const float e0x = fmaf(sn1, T2.x, fmaf(cn1, T1.x, T0.x));
        const float e0y = fmaf(sn1, T2.y, fmaf(cn1, T1.y, T0.y));
        const float e1x = fmaf(sn1, T5.x, fmaf(cn1, T4.x, T3.x));
        const float e1y = fmaf(sn1, T5.y, fmaf(cn1, T4.y, T3.y));
        const float e2x = fmaf(sn1, T8.x, fmaf(cn1, T7.x, T6.x));
        const float e2y = fmaf(sn1, T8.y, fmaf(cn1, T7.y, T6.y));
        float rx = fmaf(sn0, e2x, fmaf(cn0, e1x, e0x));
        float ry = fmaf(sn0, e2y, fmaf(cn0, e1y, e0y));
        rx = fmaf(cn2, U0.x, rx);  ry = fmaf(cn2, U0.y, ry);
        rx = fmaf(sn2, U1.x, rx);  ry = fmaf(sn2, U1.y, ry);
        rx = fmaf(cn3, U2.x, rx);  ry = fmaf(cn3, U2.y, ry);
        rx = fmaf(sn3, U3.x, rx);  ry = fmaf(sn3, U3.y, ry);
        out2[(size_t)c * CHUNK + t] = make_float2(rx, ry);

        __syncthreads();   // all reads of buf[cur] done before its reuse
    }

    // ---- remainder tail (B % CHUNK), handled by block 0 with direct loads
    if (blockIdx.x == 0) {
        const int tail = nchunks * CHUNK;
        for (int i = tail + t; i < B; i += 256) {
            const float4 xv = x4[i];
            float sn0, cn0, sn1, cn1, sn2, cn2, sn3, cn3;
            __sincosf(xv.x, &sn0, &cn0);
            __sincosf(xv.y, &sn1, &cn1);
            __sincosf(xv.z, &sn2, &cn2);
            __sincosf(xv.w, &sn3, &cn3);
            const float e0x = fmaf(sn1, T2.x, fmaf(cn1, T1.x, T0.x));
            const float e0y = fmaf(sn1, T2.y, fmaf(cn1, T1.y, T0.y));
            const float e1x = fmaf(sn1, T5.x, fmaf(cn1, T4.x, T3.x));
            const float e1y = fmaf(sn1, T5.y, fmaf(cn1, T4.y, T3.y));
            const float e2x = fmaf(sn1, T8.x, fmaf(cn1, T7.x, T6.x));
            const float e2y = fmaf(sn1, T8.y, fmaf(cn1, T7.y, T6.y));
            float rx = fmaf(sn0, e2x, fmaf(cn0, e1x, e0x));
            float ry = fmaf(sn0, e2y, fmaf(cn0, e1y, e0y));
            rx = fmaf(cn2, U0.x, rx);  ry = fmaf(cn2, U0.y, ry);
            rx = fmaf(sn2, U1.x, rx);  ry = fmaf(sn2, U1.y, ry);
            rx = fmaf(cn3, U2.x, rx);  ry = fmaf(cn3, U2.y, ry);
            rx = fmaf(sn3, U3.x, rx);  ry = fmaf(sn3, U3.y, ry);
            out2[i] = make_float2(rx, ry);
        }
    }
}

extern "C" void kernel_launch(void* const* d_in, const int* in_sizes, int n_in,
                              void* d_out, int out_size) {
    const float* x  = (const float*)d_in[0];   // (B, 4) fp32
    const float* w  = (const float*)d_in[1];   // (2, 4, 4) fp32
    const float* hw = (const float*)d_in[2];   // (2, 4) fp32
    const float* hb = (const float*)d_in[3];   // (2,) fp32

    const int B = in_sizes[0] / 4;
    const int nchunks = B / CHUNK;             // full 256-sample chunks
    int grid = 592;                            // 4 blocks/SM x 148 SMs
    if (grid > nchunks && nchunks > 0) grid = nchunks;
    if (nchunks == 0) grid = 1;

    fused_kernel<<<grid, 256>>>((const float4*)x, (float2*)d_out,
                                w, hw, hb, nchunks, B);
}